// round 13
// baseline (speedup 1.0000x reference)
#include <cuda_runtime.h>
#include <cuda_fp16.h>
#include <math.h>
#include <stdint.h>

#define NMAX 50000
#define EMAX 800000
#define CIN 64
#define COUT 128
#define NH 4
#define BUCKET 128

// ---------------- scratch ----------------------------------------------------
__device__ __align__(8) int g_nd[NMAX * 2];    // [2i]=count, [2i+1]=deg (float bits)
__device__ float    g_dinv[NMAX];
__device__ float    g_btt[COUT];
__device__ unsigned g_fill;
__device__ uint2    g_bucket[NMAX * BUCKET];   // {row, w_bits} per edge
__device__ __half   g_xwh [NMAX * COUT];       // gemm outputs (fp16)
__device__ __half   g_cvh [NMAX * COUT];       // conv outputs (fp16)
__device__ __half   g_hah [NMAX * COUT];       // fp16 attention features
__device__ float    g_res [NMAX * COUT];
__device__ float    g_als [NMAX * NH];
__device__ float    g_ald [NMAX * NH];

// ---------------- helpers ----------------------------------------------------
__device__ __forceinline__ float lrelu(float v, float s) { return v > 0.f ? v : s * v; }
__device__ __forceinline__ unsigned encf(float f) {
    unsigned u = __float_as_uint(f);
    return (u & 0x80000000u) ? ~u : (u | 0x80000000u);
}
__device__ __forceinline__ float decf(unsigned u) {
    return (u & 0x80000000u) ? __uint_as_float(u & 0x7fffffffu) : __uint_as_float(~u);
}
__device__ __forceinline__ unsigned f2tf32(float f) {
    unsigned u; asm("cvt.rna.tf32.f32 %0, %1;" : "=r"(u) : "f"(f)); return u;
}
__device__ __forceinline__ void mma_tf32(float* c, const unsigned* a, const unsigned* b) {
    asm("mma.sync.aligned.m16n8k8.row.col.f32.tf32.tf32.f32 "
        "{%0,%1,%2,%3}, {%4,%5,%6,%7}, {%8,%9}, {%0,%1,%2,%3};"
        : "+f"(c[0]), "+f"(c[1]), "+f"(c[2]), "+f"(c[3])
        : "r"(a[0]), "r"(a[1]), "r"(a[2]), "r"(a[3]), "r"(b[0]), "r"(b[1]));
}

// ---------------- setup ------------------------------------------------------
__global__ void k_init(const float* __restrict__ teb, const float* __restrict__ b1, int n) {
    int i = blockIdx.x * blockDim.x + threadIdx.x;
    if (i == 0) g_fill = 0u;
    if (i < COUT) g_btt[i] = teb[i] + b1[i];
    if (i < n) {
        g_nd[2 * i]     = 0;
        g_nd[2 * i + 1] = 0x3f800000;   // deg = 1.0f (self loop)
    }
}

// ONE edge pass: count + weighted degree + bucket store + max(ew)
__global__ void k_place(const int* __restrict__ row, const int* __restrict__ col,
                        const float* __restrict__ ew, int E) {
    int e = blockIdx.x * blockDim.x + threadIdx.x;
    float w = 0.f;
    if (e < E) {
        int c = col[e];
        int r = row[e];
        w = ew[e];
        atomicAdd((float*)&g_nd[2 * c + 1], w);
        int slot = atomicAdd(&g_nd[2 * c], 1);
        if (slot < BUCKET)
            g_bucket[c * BUCKET + slot] = make_uint2((unsigned)r, __float_as_uint(w));
    }
    #pragma unroll
    for (int off = 16; off; off >>= 1) w = fmaxf(w, __shfl_down_sync(0xffffffffu, w, off));
    __shared__ float sm[8];
    int lane = threadIdx.x & 31, wid = threadIdx.x >> 5;
    if (lane == 0) sm[wid] = w;
    __syncthreads();
    if (threadIdx.x == 0) {
        float m = sm[0];
        #pragma unroll
        for (int i2 = 1; i2 < 8; i2++) m = fmaxf(m, sm[i2]);
        atomicMax(&g_fill, encf(m));
    }
}

__global__ void k_dinv(int n) {
    int i = blockIdx.x * blockDim.x + threadIdx.x;
    if (i < n) g_dinv[i] = rsqrtf(__int_as_float(g_nd[2 * i + 1]));
}

__global__ void k_tt_partial(const float* __restrict__ t, const float* __restrict__ tew) {
    int j = threadIdx.x;
    int k0 = blockIdx.x * 16;
    float acc = 0.f;
    #pragma unroll
    for (int k = 0; k < 16; k++) acc += lrelu(t[k0 + k], 0.01f) * tew[(k0 + k) * COUT + j];
    atomicAdd(&g_btt[j], acc);
}

// ---------------- tf32 TC GEMM: [n,K] @ [K,128], panel-staged, 2-4 barriers --
// As = [128 rows][68] holds one 64-wide K panel. Ws = [K][136].
template <int K, int BIAS, int OUTH, int GN0, int AL, int INH>
__global__ __launch_bounds__(256, 2)
void k_gemm_tc(const float* __restrict__ A, const __half* __restrict__ Ah,
               const float* __restrict__ W,
               const float* __restrict__ bias, float* __restrict__ out,
               __half* __restrict__ outh, const float* __restrict__ gnw,
               const float* __restrict__ gnb, const float* __restrict__ asrc,
               const float* __restrict__ adst, int n) {
    extern __shared__ unsigned smemu[];
    unsigned* Ws = smemu;              // [K][136]
    unsigned* As = smemu + K * 136;    // [128][68]
    const int PHASES = K / 64;
    int tid = threadIdx.x;
    for (int i = tid; i < K * 128; i += 256) {
        int k = i >> 7, j = i & 127;
        Ws[k * 136 + j] = f2tf32(W[i]);
    }
    int lane = tid & 31, w = tid >> 5;
    int wm = (w & 3) * 32;
    int wn = (w >> 2) * 64;
    int r = lane >> 2, q = lane & 3;
    int arow = tid >> 1;               // staging: 2 threads per row
    int kb = (tid & 1) * 32;           // each covers 32 K values
    int tiles = (n + 127) >> 7;

    float asr[2][8], adr[2][8];
    int hbase = wn >> 5;
    if (AL) {
        #pragma unroll
        for (int hh = 0; hh < 2; hh++)
            #pragma unroll
            for (int j = 0; j < 4; j++)
                #pragma unroll
                for (int i2 = 0; i2 < 2; i2++) {
                    int idx = (hbase + hh) * 32 + j * 8 + 2 * q + i2;
                    asr[hh][j * 2 + i2] = __ldg(asrc + idx);
                    adr[hh][j * 2 + i2] = __ldg(adst + idx);
                }
    }

    for (int tile = blockIdx.x; tile < tiles; tile += gridDim.x) {
        int m0 = tile << 7;
        int grow = m0 + arow;
        bool rok = grow < n;
        float c[2][8][4];
        #pragma unroll
        for (int mt = 0; mt < 2; mt++)
            #pragma unroll
            for (int nt = 0; nt < 8; nt++)
                #pragma unroll
                for (int i = 0; i < 4; i++) c[mt][nt][i] = 0.f;

        for (int ph = 0; ph < PHASES; ph++) {
            __syncthreads();           // protect As from previous readers
            // ---- stage full 64-K panel: 4 groups of 8 channels per thread ----
            #pragma unroll
            for (int i = 0; i < 4; i++) {
                int kx = kb + i * 8;           // panel-local k
                int kg = ph * 64 + kx;         // global k
                float v[8];
                if (INH) {
                    uint4 raw = make_uint4(0u, 0u, 0u, 0u);
                    if (rok) raw = *(const uint4*)(Ah + (size_t)grow * K + kg);
                    __half2* hp = (__half2*)&raw;
                    float2 f0 = __half22float2(hp[0]), f1 = __half22float2(hp[1]);
                    float2 f2 = __half22float2(hp[2]), f3 = __half22float2(hp[3]);
                    v[0] = f0.x; v[1] = f0.y; v[2] = f1.x; v[3] = f1.y;
                    v[4] = f2.x; v[5] = f2.y; v[6] = f3.x; v[7] = f3.y;
                } else {
                    float4 v0 = make_float4(0.f,0.f,0.f,0.f), v1 = v0;
                    if (rok) {
                        const float* ap = A + (size_t)grow * K + kg;
                        v0 = *(const float4*)ap;
                        v1 = *(const float4*)(ap + 4);
                    }
                    v[0] = v0.x; v[1] = v0.y; v[2] = v0.z; v[3] = v0.w;
                    v[4] = v1.x; v[5] = v1.y; v[6] = v1.z; v[7] = v1.w;
                }
                if (GN0) {             // 8 contiguous channels = one GN group
                    float s = 0.f, ss = 0.f;
                    #pragma unroll
                    for (int j = 0; j < 8; j++) { s += v[j]; ss += v[j] * v[j]; }
                    float mean = s * 0.125f;
                    float var  = ss * 0.125f - mean * mean;
                    float inv  = rsqrtf(var + 1e-5f);
                    #pragma unroll
                    for (int j = 0; j < 8; j++)
                        v[j] = lrelu((v[j] - mean) * inv * __ldg(gnw + kg + j)
                                     + __ldg(gnb + kg + j), 0.01f);
                }
                unsigned* d = As + arow * 68 + kx;
                #pragma unroll
                for (int j = 0; j < 8; j++) d[j] = f2tf32(v[j]);
            }
            __syncthreads();
            // ---- 8 uninterrupted kk chunks ----
            #pragma unroll
            for (int kk = 0; kk < 64; kk += 8) {
                unsigned a[2][4];
                #pragma unroll
                for (int mt = 0; mt < 2; mt++) {
                    const unsigned* ap = As + (wm + mt * 16 + r) * 68 + kk + q;
                    a[mt][0] = ap[0];
                    a[mt][1] = ap[8 * 68];
                    a[mt][2] = ap[4];
                    a[mt][3] = ap[8 * 68 + 4];
                }
                #pragma unroll
                for (int nt = 0; nt < 8; nt++) {
                    unsigned b[2];
                    const unsigned* bp = Ws + (ph * 64 + kk + q) * 136 + wn + nt * 8 + r;
                    b[0] = bp[0];
                    b[1] = bp[4 * 136];
                    mma_tf32(c[0][nt], a[0], b);
                    mma_tf32(c[1][nt], a[1], b);
                }
            }
        }
        // ---- epilogue ----
        #pragma unroll
        for (int mt = 0; mt < 2; mt++) {
            #pragma unroll
            for (int rr = 0; rr < 2; rr++) {
                int m = m0 + wm + mt * 16 + r + rr * 8;
                if (m < n) {
                    #pragma unroll
                    for (int nt = 0; nt < 8; nt++) {
                        int col = wn + nt * 8 + 2 * q;
                        float v0 = c[mt][nt][rr * 2 + 0];
                        float v1 = c[mt][nt][rr * 2 + 1];
                        if (BIAS) { v0 += bias[col]; v1 += bias[col + 1]; }
                        if (OUTH) {
                            *(__half2*)(outh + (size_t)m * 128 + col) = __floats2half2_rn(v0, v1);
                        } else {
                            *(float2*)(out + (size_t)m * 128 + col) = make_float2(v0, v1);
                        }
                    }
                }
                if (AL) {
                    float sA0 = 0.f, sA1 = 0.f, sD0 = 0.f, sD1 = 0.f;
                    #pragma unroll
                    for (int j = 0; j < 4; j++)
                        #pragma unroll
                        for (int i2 = 0; i2 < 2; i2++) {
                            float c0 = c[mt][j][rr * 2 + i2];
                            float c1 = c[mt][4 + j][rr * 2 + i2];
                            sA0 += c0 * asr[0][j * 2 + i2];
                            sD0 += c0 * adr[0][j * 2 + i2];
                            sA1 += c1 * asr[1][j * 2 + i2];
                            sD1 += c1 * adr[1][j * 2 + i2];
                        }
                    sA0 += __shfl_xor_sync(0xffffffffu, sA0, 1);
                    sA0 += __shfl_xor_sync(0xffffffffu, sA0, 2);
                    sA1 += __shfl_xor_sync(0xffffffffu, sA1, 1);
                    sA1 += __shfl_xor_sync(0xffffffffu, sA1, 2);
                    sD0 += __shfl_xor_sync(0xffffffffu, sD0, 1);
                    sD0 += __shfl_xor_sync(0xffffffffu, sD0, 2);
                    sD1 += __shfl_xor_sync(0xffffffffu, sD1, 1);
                    sD1 += __shfl_xor_sync(0xffffffffu, sD1, 2);
                    if (q == 0 && m < n) {
                        g_als[m * 4 + hbase]     = sA0;
                        g_als[m * 4 + hbase + 1] = sA1;
                        g_ald[m * 4 + hbase]     = sD0;
                        g_ald[m * 4 + hbase + 1] = sD1;
                    }
                }
            }
        }
    }
}

// ---------------- GCN conv (fp16 gather) + fused GN + lrelu, fp16 out --------
template <int BASEVEC>
__global__ void k_conv(const __half* __restrict__ srch, const float* __restrict__ basep,
                       __half* __restrict__ dsth,
                       const float* __restrict__ gnw, const float* __restrict__ gnb, int n) {
    int gw = (blockIdx.x * blockDim.x + threadIdx.x) >> 5;
    int lane = threadIdx.x & 31;
    if (gw >= n) return;
    int c = gw;
    int cnt = min(g_nd[2 * c], BUCKET);
    int base = c * BUCKET;
    float dc = g_dinv[c];
    float4 bb = BASEVEC ? *(const float4*)(g_btt + lane * 4)
                        : *(const float4*)(basep + (size_t)c * 128 + lane * 4);
    float d2 = dc * dc;
    float4 acc;
    {
        float2 raw = *(const float2*)(srch + (size_t)c * 128 + lane * 4);
        __half2* hp = (__half2*)&raw;
        float2 lo = __half22float2(hp[0]), hi = __half22float2(hp[1]);
        acc.x = bb.x + d2 * lo.x; acc.y = bb.y + d2 * lo.y;
        acc.z = bb.z + d2 * hi.x; acc.w = bb.w + d2 * hi.y;
    }
    for (int b0 = 0; b0 < cnt; b0 += 32) {
        int bc = min(32, cnt - b0);
        unsigned ridx = 0u; float cw = 0.f;
        if (lane < bc) {
            uint2 e2 = g_bucket[base + b0 + lane];
            ridx = e2.x;
            cw = g_dinv[(int)e2.x] * __uint_as_float(e2.y) * dc;
        }
        for (int j = 0; j < bc; j++) {
            int r = (int)__shfl_sync(0xffffffffu, ridx, j);
            float coef = __shfl_sync(0xffffffffu, cw, j);
            float2 raw = *(const float2*)(srch + (size_t)r * 128 + lane * 4);
            __half2* hp = (__half2*)&raw;
            float2 lo = __half22float2(hp[0]), hi = __half22float2(hp[1]);
            acc.x += coef * lo.x; acc.y += coef * lo.y;
            acc.z += coef * hi.x; acc.w += coef * hi.y;
        }
    }
    float s  = acc.x + acc.y + acc.z + acc.w;
    float ss = acc.x * acc.x + acc.y * acc.y + acc.z * acc.z + acc.w * acc.w;
    s  += __shfl_xor_sync(0xffffffffu, s, 1);  ss += __shfl_xor_sync(0xffffffffu, ss, 1);
    s  += __shfl_xor_sync(0xffffffffu, s, 2);  ss += __shfl_xor_sync(0xffffffffu, ss, 2);
    float mean = s * (1.f / 16.f);
    float var  = ss * (1.f / 16.f) - mean * mean;
    float inv  = rsqrtf(var + 1e-5f);
    float4 wv = *(const float4*)(gnw + lane * 4);
    float4 bv = *(const float4*)(gnb + lane * 4);
    float ox = lrelu((acc.x - mean) * inv * wv.x + bv.x, 0.01f);
    float oy = lrelu((acc.y - mean) * inv * wv.y + bv.y, 0.01f);
    float oz = lrelu((acc.z - mean) * inv * wv.z + bv.z, 0.01f);
    float ow = lrelu((acc.w - mean) * inv * wv.w + bv.w, 0.01f);
    __half2* hp = (__half2*)(dsth + (size_t)c * 128 + lane * 4);
    hp[0] = __floats2half2_rn(ox, oy);
    hp[1] = __floats2half2_rn(oz, ow);
}

// ---------------- fused GAT: single-pass, deferred-rescale online softmax ----
__global__ __launch_bounds__(256)
void k_attn(const float* __restrict__ aedge, const float* __restrict__ ba,
            float* __restrict__ out, int n) {
    int gw = (blockIdx.x * blockDim.x + threadIdx.x) >> 5;
    int lane = threadIdx.x & 31;
    if (gw >= n) return;
    int c = gw;
    int cnt = min(g_nd[2 * c], BUCKET);
    int base = c * BUCKET;
    int h = lane >> 3;
    float aeh = __ldg(aedge + h);
    float adh = __ldg(g_ald + c * 4 + h);
    float ash = __ldg(g_als + c * 4 + h);
    float fill = decf(g_fill);
    float m = lrelu(ash + adh + aeh * fill, 0.2f);   // self logit
    float tsum = 1.f;
    float4 acc;
    {
        float2 raw = *(const float2*)(g_hah + (size_t)c * 128 + lane * 4);
        __half2* hp = (__half2*)&raw;
        float2 lo = __half22float2(hp[0]), hi = __half22float2(hp[1]);
        acc.x = lo.x; acc.y = lo.y; acc.z = hi.x; acc.w = hi.y;
    }
    for (int b0 = 0; b0 < cnt; b0 += 32) {
        int bc = min(32, cnt - b0);
        unsigned ridx = 0u; float wreg = 0.f;
        float4 a4 = make_float4(0.f, 0.f, 0.f, 0.f);
        if (lane < bc) {
            uint2 e2 = g_bucket[base + b0 + lane];
            ridx = e2.x;
            wreg = __uint_as_float(e2.y);
            a4 = *(const float4*)(g_als + (int)e2.x * 4);   // prefetch, MLP=32
        }
        for (int j = 0; j < bc; j++) {
            int r    = (int)__shfl_sync(0xffffffffu, ridx, j);
            float w  = __shfl_sync(0xffffffffu, wreg, j);
            float ax = __shfl_sync(0xffffffffu, a4.x, j);
            float ay = __shfl_sync(0xffffffffu, a4.y, j);
            float az = __shfl_sync(0xffffffffu, a4.z, j);
            float aw = __shfl_sync(0xffffffffu, a4.w, j);
            float asr = (h == 0) ? ax : (h == 1) ? ay : (h == 2) ? az : aw;
            float l = lrelu(asr + adh + aeh * w, 0.2f);
            float e;
            if (l > m) {                       // rare: rescale history
                float sc = __expf(m - l);
                tsum *= sc;
                acc.x *= sc; acc.y *= sc; acc.z *= sc; acc.w *= sc;
                m = l;
                e = 1.f;
            } else {
                e = __expf(l - m);             // off the loop-carried chain
            }
            tsum += e;
            float2 raw = *(const float2*)(g_hah + (size_t)r * 128 + lane * 4);
            __half2* hp = (__half2*)&raw;
            float2 lo = __half22float2(hp[0]), hi = __half22float2(hp[1]);
            acc.x += e * lo.x; acc.y += e * lo.y;
            acc.z += e * hi.x; acc.w += e * hi.y;
        }
    }
    float rs = 1.f / (tsum + 1e-16f);
    float4 bav = *(const float4*)(ba + lane * 4);
    float4 o;
    o.x = bav.x + acc.x * rs;
    o.y = bav.y + acc.y * rs;
    o.z = bav.z + acc.z * rs;
    o.w = bav.w + acc.w * rs;
    *(float4*)(out + (size_t)c * 128 + lane * 4) = o;
}

// ---------------- launch -----------------------------------------------------
extern "C" void kernel_launch(void* const* d_in, const int* in_sizes, int n_in,
                              void* d_out, int out_size) {
    const float* x    = (const float*)d_in[0];
    const float* t    = (const float*)d_in[1];
    const int*   ei   = (const int*)  d_in[2];
    const float* ew   = (const float*)d_in[3];
    const float* gn0w = (const float*)d_in[4];
    const float* gn0b = (const float*)d_in[5];
    const float* W1   = (const float*)d_in[6];
    const float* b1   = (const float*)d_in[7];
    const float* gn1w = (const float*)d_in[8];
    const float* gn1b = (const float*)d_in[9];
    const float* W2   = (const float*)d_in[10];
    const float* b2   = (const float*)d_in[11];
    const float* Wres = (const float*)d_in[12];
    const float* tew  = (const float*)d_in[13];
    const float* teb  = (const float*)d_in[14];
    const float* gn2w = (const float*)d_in[15];
    const float* gn2b = (const float*)d_in[16];
    const float* Wa   = (const float*)d_in[17];
    const float* asrc = (const float*)d_in[18];
    const float* adst = (const float*)d_in[19];
    const float* aedg = (const float*)d_in[20];
    const float* ba   = (const float*)d_in[21];

    int n = in_sizes[0] / CIN;
    int E = in_sizes[3];
    const int* row  = ei;
    const int* colp = ei + E;
    float* out = (float*)d_out;

    const int SM64  = (64 * 136 + 128 * 68) * 4;    // 69632
    const int SM128 = (128 * 136 + 128 * 68) * 4;   // 104448

    static cudaStream_t s1 = nullptr, s2 = nullptr;
    static cudaEvent_t evInit = nullptr, evCSR = nullptr, evAux = nullptr;
    if (!s1) {
        cudaStreamCreateWithFlags(&s1, cudaStreamNonBlocking);
        cudaStreamCreateWithFlags(&s2, cudaStreamNonBlocking);
        cudaEventCreateWithFlags(&evInit, cudaEventDisableTiming);
        cudaEventCreateWithFlags(&evCSR,  cudaEventDisableTiming);
        cudaEventCreateWithFlags(&evAux,  cudaEventDisableTiming);
        cudaFuncSetAttribute(k_gemm_tc<CIN, 0, 1, 1, 0, 0>,  cudaFuncAttributeMaxDynamicSharedMemorySize, SM64);
        cudaFuncSetAttribute(k_gemm_tc<CIN, 1, 0, 0, 0, 0>,  cudaFuncAttributeMaxDynamicSharedMemorySize, SM64);
        cudaFuncSetAttribute(k_gemm_tc<COUT, 0, 1, 0, 0, 1>, cudaFuncAttributeMaxDynamicSharedMemorySize, SM128);
        cudaFuncSetAttribute(k_gemm_tc<COUT, 0, 1, 0, 1, 1>, cudaFuncAttributeMaxDynamicSharedMemorySize, SM128);
    }

    float *p_res;
    __half *p_xwh, *p_cvh, *p_hah;
    cudaGetSymbolAddress((void**)&p_xwh, g_xwh);
    cudaGetSymbolAddress((void**)&p_cvh, g_cvh);
    cudaGetSymbolAddress((void**)&p_hah, g_hah);
    cudaGetSymbolAddress((void**)&p_res, g_res);

    const int T = 256;
    int gN  = (n + T - 1) / T;
    int gE  = (E + T - 1) / T;
    int gNW = (n * 32 + T - 1) / T;
    const int GG = 296;

    k_init<<<gN, T>>>(teb, b1, n);
    cudaEventRecord(evInit, 0);

    // s1: bucketed CSR build
    cudaStreamWaitEvent(s1, evInit, 0);
    k_place<<<gE, T, 0, s1>>>(row, colp, ew, E);
    k_dinv<<<gN, T, 0, s1>>>(n);
    cudaEventRecord(evCSR, s1);

    // s2: residual GEMM + time embed
    cudaStreamWaitEvent(s2, evInit, 0);
    k_gemm_tc<CIN, 1, 0, 0, 0, 0><<<GG, 256, SM64, s2>>>(x, nullptr, Wres, b2, p_res, nullptr,
                                                         nullptr, nullptr, nullptr, nullptr, n);
    k_tt_partial<<<32, 128, 0, s2>>>(t, tew);
    cudaEventRecord(evAux, s2);

    // main chain
    k_gemm_tc<CIN, 0, 1, 1, 0, 0><<<GG, 256, SM64>>>(x, nullptr, W1, nullptr, nullptr, p_xwh,
                                                     gn0w, gn0b, nullptr, nullptr, n);
    cudaStreamWaitEvent(0, evCSR, 0);
    cudaStreamWaitEvent(0, evAux, 0);
    k_conv<1><<<gNW, T>>>(p_xwh, nullptr, p_cvh, gn1w, gn1b, n);

    k_gemm_tc<COUT, 0, 1, 0, 0, 1><<<GG, 256, SM128>>>(nullptr, p_cvh, W2, nullptr, nullptr, p_xwh,
                                                       nullptr, nullptr, nullptr, nullptr, n);
    k_conv<0><<<gNW, T>>>(p_xwh, p_res, p_cvh, gn2w, gn2b, n);

    k_gemm_tc<COUT, 0, 1, 0, 1, 1><<<GG, 256, SM128>>>(nullptr, p_cvh, Wa, nullptr, nullptr, p_hah,
                                                       nullptr, nullptr, asrc, adst, n);
    k_attn<<<gNW, T>>>(aedg, ba, out, n);
}

// round 16
// speedup vs baseline: 1.0913x; 1.0913x over previous
#include <cuda_runtime.h>
#include <cuda_fp16.h>
#include <math.h>
#include <stdint.h>

#define NMAX 50000
#define EMAX 800000
#define CIN 64
#define COUT 128
#define NH 4
#define BUCKET 128

// ---------------- scratch ----------------------------------------------------
__device__ __align__(8) int g_nd[NMAX * 2];    // [2i]=count, [2i+1]=deg (float bits)
__device__ float    g_dinv[NMAX];
__device__ float    g_btt[COUT];
__device__ unsigned g_fill;
__device__ uint2    g_bucket[NMAX * BUCKET];   // {row, w_bits} per edge
__device__ __half   g_xwh [NMAX * COUT];       // gemm outputs (fp16)
__device__ __half   g_cvh [NMAX * COUT];       // conv outputs (fp16)
__device__ __half   g_hah [NMAX * COUT];       // fp16 attention features
__device__ float    g_res [NMAX * COUT];
__device__ float    g_als [NMAX * NH];
__device__ float    g_ald [NMAX * NH];

// ---------------- helpers ----------------------------------------------------
__device__ __forceinline__ float lrelu(float v, float s) { return v > 0.f ? v : s * v; }
__device__ __forceinline__ unsigned encf(float f) {
    unsigned u = __float_as_uint(f);
    return (u & 0x80000000u) ? ~u : (u | 0x80000000u);
}
__device__ __forceinline__ float decf(unsigned u) {
    return (u & 0x80000000u) ? __uint_as_float(u & 0x7fffffffu) : __uint_as_float(~u);
}
__device__ __forceinline__ unsigned h2u(__half2 h) {
    union { __half2 h; unsigned u; } cv; cv.h = h; return cv.u;
}
// fp16 MMA, fp32 accumulate: m16n8k16
__device__ __forceinline__ void mma_f16(float* c, const unsigned* a, const unsigned* b) {
    asm("mma.sync.aligned.m16n8k16.row.col.f32.f16.f16.f32 "
        "{%0,%1,%2,%3}, {%4,%5,%6,%7}, {%8,%9}, {%0,%1,%2,%3};"
        : "+f"(c[0]), "+f"(c[1]), "+f"(c[2]), "+f"(c[3])
        : "r"(a[0]), "r"(a[1]), "r"(a[2]), "r"(a[3]), "r"(b[0]), "r"(b[1]));
}

// ---------------- setup ------------------------------------------------------
__global__ void k_init(const float* __restrict__ teb, const float* __restrict__ b1, int n) {
    int i = blockIdx.x * blockDim.x + threadIdx.x;
    if (i == 0) g_fill = 0u;
    if (i < COUT) g_btt[i] = teb[i] + b1[i];
    if (i < n) {
        g_nd[2 * i]     = 0;
        g_nd[2 * i + 1] = 0x3f800000;   // deg = 1.0f (self loop)
    }
}

// ONE edge pass: count + weighted degree + bucket store + max(ew)
__global__ void k_place(const int* __restrict__ row, const int* __restrict__ col,
                        const float* __restrict__ ew, int E) {
    int e = blockIdx.x * blockDim.x + threadIdx.x;
    float w = 0.f;
    if (e < E) {
        int c = col[e];
        int r = row[e];
        w = ew[e];
        atomicAdd((float*)&g_nd[2 * c + 1], w);
        int slot = atomicAdd(&g_nd[2 * c], 1);
        if (slot < BUCKET)
            g_bucket[c * BUCKET + slot] = make_uint2((unsigned)r, __float_as_uint(w));
    }
    #pragma unroll
    for (int off = 16; off; off >>= 1) w = fmaxf(w, __shfl_down_sync(0xffffffffu, w, off));
    __shared__ float sm[8];
    int lane = threadIdx.x & 31, wid = threadIdx.x >> 5;
    if (lane == 0) sm[wid] = w;
    __syncthreads();
    if (threadIdx.x == 0) {
        float m = sm[0];
        #pragma unroll
        for (int i2 = 1; i2 < 8; i2++) m = fmaxf(m, sm[i2]);
        atomicMax(&g_fill, encf(m));
    }
}

__global__ void k_dinv(int n) {
    int i = blockIdx.x * blockDim.x + threadIdx.x;
    if (i < n) g_dinv[i] = rsqrtf(__int_as_float(g_nd[2 * i + 1]));
}

__global__ void k_tt_partial(const float* __restrict__ t, const float* __restrict__ tew) {
    int j = threadIdx.x;
    int k0 = blockIdx.x * 16;
    float acc = 0.f;
    #pragma unroll
    for (int k = 0; k < 16; k++) acc += lrelu(t[k0 + k], 0.01f) * tew[(k0 + k) * COUT + j];
    atomicAdd(&g_btt[j], acc);
}

// ---------------- fp16 TC GEMM: [n,K] @ [K,128], m16n8k16 --------------------
// Wst[n][k] transposed in smem (half, pitch K+8). As[row][k] half, pitch K+8.
template <int K, int BIAS, int OUTH, int GN0, int AL, int INH>
__global__ __launch_bounds__(256, 2)
void k_gemm_tc(const float* __restrict__ A, const __half* __restrict__ Ah,
               const float* __restrict__ W,
               const float* __restrict__ bias, float* __restrict__ out,
               __half* __restrict__ outh, const float* __restrict__ gnw,
               const float* __restrict__ gnb, const float* __restrict__ asrc,
               const float* __restrict__ adst, int n) {
    extern __shared__ __half smemh[];
    const int WP = K + 8;
    __half* Ws = smemh;                // [128 n][WP]
    __half* As = smemh + 128 * WP;     // [128 row][WP]
    const int PHASES = K / 64;
    int tid = threadIdx.x;
    // stage W transposed (one-time)
    for (int i = tid; i < K * 128; i += 256) {
        int k = i >> 7, j = i & 127;
        Ws[j * WP + k] = __float2half_rn(W[i]);
    }
    int lane = tid & 31, w = tid >> 5;
    int wm = (w & 3) * 32;
    int wn = (w >> 2) * 64;
    int r = lane >> 2, q = lane & 3;
    int arow = tid >> 1;               // staging: 2 threads per row
    int kb = (tid & 1) * 32;           // each covers 32 K values per phase
    int tiles = (n + 127) >> 7;

    float asr[2][8], adr[2][8];
    int hbase = wn >> 5;
    if (AL) {
        #pragma unroll
        for (int hh = 0; hh < 2; hh++)
            #pragma unroll
            for (int j = 0; j < 4; j++)
                #pragma unroll
                for (int i2 = 0; i2 < 2; i2++) {
                    int idx = (hbase + hh) * 32 + j * 8 + 2 * q + i2;
                    asr[hh][j * 2 + i2] = __ldg(asrc + idx);
                    adr[hh][j * 2 + i2] = __ldg(adst + idx);
                }
    }

    for (int tile = blockIdx.x; tile < tiles; tile += gridDim.x) {
        int m0 = tile << 7;
        int grow = m0 + arow;
        bool rok = grow < n;
        float c[2][8][4];
        #pragma unroll
        for (int mt = 0; mt < 2; mt++)
            #pragma unroll
            for (int nt = 0; nt < 8; nt++)
                #pragma unroll
                for (int i = 0; i < 4; i++) c[mt][nt][i] = 0.f;

        for (int ph = 0; ph < PHASES; ph++) {
            __syncthreads();
            // ---- stage 64-K panel: 4 groups of 8 values per thread ----
            #pragma unroll
            for (int i = 0; i < 4; i++) {
                int kx = kb + i * 8;
                int kg = ph * 64 + kx;
                __half* d = As + arow * WP + kg;
                if (INH) {
                    uint4 raw = make_uint4(0u, 0u, 0u, 0u);
                    if (rok) raw = *(const uint4*)(Ah + (size_t)grow * K + kg);
                    *(uint4*)d = raw;            // straight fp16 copy
                } else {
                    float4 v0 = make_float4(0.f,0.f,0.f,0.f), v1 = v0;
                    if (rok) {
                        const float* ap = A + (size_t)grow * K + kg;
                        v0 = *(const float4*)ap;
                        v1 = *(const float4*)(ap + 4);
                    }
                    float v[8] = {v0.x, v0.y, v0.z, v0.w, v1.x, v1.y, v1.z, v1.w};
                    if (GN0) {         // 8 contiguous channels = one GN group
                        float s = 0.f, ss = 0.f;
                        #pragma unroll
                        for (int j = 0; j < 8; j++) { s += v[j]; ss += v[j] * v[j]; }
                        float mean = s * 0.125f;
                        float var  = ss * 0.125f - mean * mean;
                        float inv  = rsqrtf(var + 1e-5f);
                        #pragma unroll
                        for (int j = 0; j < 8; j++)
                            v[j] = lrelu((v[j] - mean) * inv * __ldg(gnw + kg + j)
                                         + __ldg(gnb + kg + j), 0.01f);
                    }
                    uint4 pk;
                    pk.x = h2u(__floats2half2_rn(v[0], v[1]));
                    pk.y = h2u(__floats2half2_rn(v[2], v[3]));
                    pk.z = h2u(__floats2half2_rn(v[4], v[5]));
                    pk.w = h2u(__floats2half2_rn(v[6], v[7]));
                    *(uint4*)d = pk;
                }
            }
            __syncthreads();
            // ---- 4 kk chunks of K=16 each ----
            #pragma unroll
            for (int kk = 0; kk < 64; kk += 16) {
                int kgl = ph * 64 + kk;
                unsigned a[2][4];
                #pragma unroll
                for (int mt = 0; mt < 2; mt++) {
                    const __half* ap0 = As + (wm + mt * 16 + r) * WP + kgl + 2 * q;
                    const __half* ap1 = ap0 + 8 * WP;
                    a[mt][0] = *(const unsigned*)ap0;
                    a[mt][1] = *(const unsigned*)ap1;
                    a[mt][2] = *(const unsigned*)(ap0 + 8);
                    a[mt][3] = *(const unsigned*)(ap1 + 8);
                }
                #pragma unroll
                for (int nt = 0; nt < 8; nt++) {
                    const __half* bp = Ws + (wn + nt * 8 + r) * WP + kgl + 2 * q;
                    unsigned b[2];
                    b[0] = *(const unsigned*)bp;
                    b[1] = *(const unsigned*)(bp + 8);
                    mma_f16(c[0][nt], a[0], b);
                    mma_f16(c[1][nt], a[1], b);
                }
            }
        }
        // ---- epilogue ----
        #pragma unroll
        for (int mt = 0; mt < 2; mt++) {
            #pragma unroll
            for (int rr = 0; rr < 2; rr++) {
                int m = m0 + wm + mt * 16 + r + rr * 8;
                if (m < n) {
                    #pragma unroll
                    for (int nt = 0; nt < 8; nt++) {
                        int col = wn + nt * 8 + 2 * q;
                        float v0 = c[mt][nt][rr * 2 + 0];
                        float v1 = c[mt][nt][rr * 2 + 1];
                        if (BIAS) { v0 += bias[col]; v1 += bias[col + 1]; }
                        if (OUTH) {
                            *(__half2*)(outh + (size_t)m * 128 + col) = __floats2half2_rn(v0, v1);
                        } else {
                            *(float2*)(out + (size_t)m * 128 + col) = make_float2(v0, v1);
                        }
                    }
                }
                if (AL) {
                    float sA0 = 0.f, sA1 = 0.f, sD0 = 0.f, sD1 = 0.f;
                    #pragma unroll
                    for (int j = 0; j < 4; j++)
                        #pragma unroll
                        for (int i2 = 0; i2 < 2; i2++) {
                            float c0 = c[mt][j][rr * 2 + i2];
                            float c1 = c[mt][4 + j][rr * 2 + i2];
                            sA0 += c0 * asr[0][j * 2 + i2];
                            sD0 += c0 * adr[0][j * 2 + i2];
                            sA1 += c1 * asr[1][j * 2 + i2];
                            sD1 += c1 * adr[1][j * 2 + i2];
                        }
                    sA0 += __shfl_xor_sync(0xffffffffu, sA0, 1);
                    sA0 += __shfl_xor_sync(0xffffffffu, sA0, 2);
                    sA1 += __shfl_xor_sync(0xffffffffu, sA1, 1);
                    sA1 += __shfl_xor_sync(0xffffffffu, sA1, 2);
                    sD0 += __shfl_xor_sync(0xffffffffu, sD0, 1);
                    sD0 += __shfl_xor_sync(0xffffffffu, sD0, 2);
                    sD1 += __shfl_xor_sync(0xffffffffu, sD1, 1);
                    sD1 += __shfl_xor_sync(0xffffffffu, sD1, 2);
                    if (q == 0 && m < n) {
                        g_als[m * 4 + hbase]     = sA0;
                        g_als[m * 4 + hbase + 1] = sA1;
                        g_ald[m * 4 + hbase]     = sD0;
                        g_ald[m * 4 + hbase + 1] = sD1;
                    }
                }
            }
        }
    }
}

// ---------------- GCN conv (fp16 gather) + fused GN + lrelu, fp16 out --------
template <int BASEVEC>
__global__ void k_conv(const __half* __restrict__ srch, const float* __restrict__ basep,
                       __half* __restrict__ dsth,
                       const float* __restrict__ gnw, const float* __restrict__ gnb, int n) {
    int gw = (blockIdx.x * blockDim.x + threadIdx.x) >> 5;
    int lane = threadIdx.x & 31;
    if (gw >= n) return;
    int c = gw;
    int cnt = min(g_nd[2 * c], BUCKET);
    int base = c * BUCKET;
    float dc = g_dinv[c];
    float4 bb = BASEVEC ? *(const float4*)(g_btt + lane * 4)
                        : *(const float4*)(basep + (size_t)c * 128 + lane * 4);
    float d2 = dc * dc;
    float4 acc;
    {
        float2 raw = *(const float2*)(srch + (size_t)c * 128 + lane * 4);
        __half2* hp = (__half2*)&raw;
        float2 lo = __half22float2(hp[0]), hi = __half22float2(hp[1]);
        acc.x = bb.x + d2 * lo.x; acc.y = bb.y + d2 * lo.y;
        acc.z = bb.z + d2 * hi.x; acc.w = bb.w + d2 * hi.y;
    }
    for (int b0 = 0; b0 < cnt; b0 += 32) {
        int bc = min(32, cnt - b0);
        unsigned ridx = 0u; float cw = 0.f;
        if (lane < bc) {
            uint2 e2 = g_bucket[base + b0 + lane];
            ridx = e2.x;
            cw = g_dinv[(int)e2.x] * __uint_as_float(e2.y) * dc;
        }
        for (int j = 0; j < bc; j++) {
            int r = (int)__shfl_sync(0xffffffffu, ridx, j);
            float coef = __shfl_sync(0xffffffffu, cw, j);
            float2 raw = *(const float2*)(srch + (size_t)r * 128 + lane * 4);
            __half2* hp = (__half2*)&raw;
            float2 lo = __half22float2(hp[0]), hi = __half22float2(hp[1]);
            acc.x += coef * lo.x; acc.y += coef * lo.y;
            acc.z += coef * hi.x; acc.w += coef * hi.y;
        }
    }
    float s  = acc.x + acc.y + acc.z + acc.w;
    float ss = acc.x * acc.x + acc.y * acc.y + acc.z * acc.z + acc.w * acc.w;
    s  += __shfl_xor_sync(0xffffffffu, s, 1);  ss += __shfl_xor_sync(0xffffffffu, ss, 1);
    s  += __shfl_xor_sync(0xffffffffu, s, 2);  ss += __shfl_xor_sync(0xffffffffu, ss, 2);
    float mean = s * (1.f / 16.f);
    float var  = ss * (1.f / 16.f) - mean * mean;
    float inv  = rsqrtf(var + 1e-5f);
    float4 wv = *(const float4*)(gnw + lane * 4);
    float4 bv = *(const float4*)(gnb + lane * 4);
    float ox = lrelu((acc.x - mean) * inv * wv.x + bv.x, 0.01f);
    float oy = lrelu((acc.y - mean) * inv * wv.y + bv.y, 0.01f);
    float oz = lrelu((acc.z - mean) * inv * wv.z + bv.z, 0.01f);
    float ow = lrelu((acc.w - mean) * inv * wv.w + bv.w, 0.01f);
    __half2* hp = (__half2*)(dsth + (size_t)c * 128 + lane * 4);
    hp[0] = __floats2half2_rn(ox, oy);
    hp[1] = __floats2half2_rn(oz, ow);
}

// ---------------- fused GAT: single-pass, deferred-rescale online softmax ----
__global__ __launch_bounds__(256)
void k_attn(const float* __restrict__ aedge, const float* __restrict__ ba,
            float* __restrict__ out, int n) {
    int gw = (blockIdx.x * blockDim.x + threadIdx.x) >> 5;
    int lane = threadIdx.x & 31;
    if (gw >= n) return;
    int c = gw;
    int cnt = min(g_nd[2 * c], BUCKET);
    int base = c * BUCKET;
    int h = lane >> 3;
    float aeh = __ldg(aedge + h);
    float adh = __ldg(g_ald + c * 4 + h);
    float ash = __ldg(g_als + c * 4 + h);
    float fill = decf(g_fill);
    float m = lrelu(ash + adh + aeh * fill, 0.2f);   // self logit
    float tsum = 1.f;
    float4 acc;
    {
        float2 raw = *(const float2*)(g_hah + (size_t)c * 128 + lane * 4);
        __half2* hp = (__half2*)&raw;
        float2 lo = __half22float2(hp[0]), hi = __half22float2(hp[1]);
        acc.x = lo.x; acc.y = lo.y; acc.z = hi.x; acc.w = hi.y;
    }
    for (int b0 = 0; b0 < cnt; b0 += 32) {
        int bc = min(32, cnt - b0);
        unsigned ridx = 0u; float wreg = 0.f;
        float4 a4 = make_float4(0.f, 0.f, 0.f, 0.f);
        if (lane < bc) {
            uint2 e2 = g_bucket[base + b0 + lane];
            ridx = e2.x;
            wreg = __uint_as_float(e2.y);
            a4 = *(const float4*)(g_als + (int)e2.x * 4);   // prefetch, MLP=32
        }
        for (int j = 0; j < bc; j++) {
            int r    = (int)__shfl_sync(0xffffffffu, ridx, j);
            float w  = __shfl_sync(0xffffffffu, wreg, j);
            float ax = __shfl_sync(0xffffffffu, a4.x, j);
            float ay = __shfl_sync(0xffffffffu, a4.y, j);
            float az = __shfl_sync(0xffffffffu, a4.z, j);
            float aw = __shfl_sync(0xffffffffu, a4.w, j);
            float asr = (h == 0) ? ax : (h == 1) ? ay : (h == 2) ? az : aw;
            float l = lrelu(asr + adh + aeh * w, 0.2f);
            float e;
            if (l > m) {                       // rare: rescale history
                float sc = __expf(m - l);
                tsum *= sc;
                acc.x *= sc; acc.y *= sc; acc.z *= sc; acc.w *= sc;
                m = l;
                e = 1.f;
            } else {
                e = __expf(l - m);             // off the loop-carried chain
            }
            tsum += e;
            float2 raw = *(const float2*)(g_hah + (size_t)r * 128 + lane * 4);
            __half2* hp = (__half2*)&raw;
            float2 lo = __half22float2(hp[0]), hi = __half22float2(hp[1]);
            acc.x += e * lo.x; acc.y += e * lo.y;
            acc.z += e * hi.x; acc.w += e * hi.y;
        }
    }
    float rs = 1.f / (tsum + 1e-16f);
    float4 bav = *(const float4*)(ba + lane * 4);
    float4 o;
    o.x = bav.x + acc.x * rs;
    o.y = bav.y + acc.y * rs;
    o.z = bav.z + acc.z * rs;
    o.w = bav.w + acc.w * rs;
    *(float4*)(out + (size_t)c * 128 + lane * 4) = o;
}

// ---------------- launch -----------------------------------------------------
extern "C" void kernel_launch(void* const* d_in, const int* in_sizes, int n_in,
                              void* d_out, int out_size) {
    const float* x    = (const float*)d_in[0];
    const float* t    = (const float*)d_in[1];
    const int*   ei   = (const int*)  d_in[2];
    const float* ew   = (const float*)d_in[3];
    const float* gn0w = (const float*)d_in[4];
    const float* gn0b = (const float*)d_in[5];
    const float* W1   = (const float*)d_in[6];
    const float* b1   = (const float*)d_in[7];
    const float* gn1w = (const float*)d_in[8];
    const float* gn1b = (const float*)d_in[9];
    const float* W2   = (const float*)d_in[10];
    const float* b2   = (const float*)d_in[11];
    const float* Wres = (const float*)d_in[12];
    const float* tew  = (const float*)d_in[13];
    const float* teb  = (const float*)d_in[14];
    const float* gn2w = (const float*)d_in[15];
    const float* gn2b = (const float*)d_in[16];
    const float* Wa   = (const float*)d_in[17];
    const float* asrc = (const float*)d_in[18];
    const float* adst = (const float*)d_in[19];
    const float* aedg = (const float*)d_in[20];
    const float* ba   = (const float*)d_in[21];

    int n = in_sizes[0] / CIN;
    int E = in_sizes[3];
    const int* row  = ei;
    const int* colp = ei + E;
    float* out = (float*)d_out;

    const int SM64  = 256 * (64 + 8) * 2;     // 36864
    const int SM128 = 256 * (128 + 8) * 2;    // 69632

    static cudaStream_t s1 = nullptr, s2 = nullptr;
    static cudaEvent_t evInit = nullptr, evCSR = nullptr, evAux = nullptr;
    if (!s1) {
        cudaStreamCreateWithFlags(&s1, cudaStreamNonBlocking);
        cudaStreamCreateWithFlags(&s2, cudaStreamNonBlocking);
        cudaEventCreateWithFlags(&evInit, cudaEventDisableTiming);
        cudaEventCreateWithFlags(&evCSR,  cudaEventDisableTiming);
        cudaEventCreateWithFlags(&evAux,  cudaEventDisableTiming);
        cudaFuncSetAttribute(k_gemm_tc<CIN, 0, 1, 1, 0, 0>,  cudaFuncAttributeMaxDynamicSharedMemorySize, SM64);
        cudaFuncSetAttribute(k_gemm_tc<CIN, 1, 0, 0, 0, 0>,  cudaFuncAttributeMaxDynamicSharedMemorySize, SM64);
        cudaFuncSetAttribute(k_gemm_tc<COUT, 0, 1, 0, 0, 1>, cudaFuncAttributeMaxDynamicSharedMemorySize, SM128);
        cudaFuncSetAttribute(k_gemm_tc<COUT, 0, 1, 0, 1, 1>, cudaFuncAttributeMaxDynamicSharedMemorySize, SM128);
    }

    float *p_res;
    __half *p_xwh, *p_cvh, *p_hah;
    cudaGetSymbolAddress((void**)&p_xwh, g_xwh);
    cudaGetSymbolAddress((void**)&p_cvh, g_cvh);
    cudaGetSymbolAddress((void**)&p_hah, g_hah);
    cudaGetSymbolAddress((void**)&p_res, g_res);

    const int T = 256;
    int gN  = (n + T - 1) / T;
    int gE  = (E + T - 1) / T;
    int gNW = (n * 32 + T - 1) / T;
    const int GG = 296;

    k_init<<<gN, T>>>(teb, b1, n);
    cudaEventRecord(evInit, 0);

    // s1: bucketed CSR build
    cudaStreamWaitEvent(s1, evInit, 0);
    k_place<<<gE, T, 0, s1>>>(row, colp, ew, E);
    k_dinv<<<gN, T, 0, s1>>>(n);
    cudaEventRecord(evCSR, s1);

    // s2: residual GEMM + time embed
    cudaStreamWaitEvent(s2, evInit, 0);
    k_gemm_tc<CIN, 1, 0, 0, 0, 0><<<GG, 256, SM64, s2>>>(x, nullptr, Wres, b2, p_res, nullptr,
                                                         nullptr, nullptr, nullptr, nullptr, n);
    k_tt_partial<<<32, 128, 0, s2>>>(t, tew);
    cudaEventRecord(evAux, s2);

    // main chain
    k_gemm_tc<CIN, 0, 1, 1, 0, 0><<<GG, 256, SM64>>>(x, nullptr, W1, nullptr, nullptr, p_xwh,
                                                     gn0w, gn0b, nullptr, nullptr, n);
    cudaStreamWaitEvent(0, evCSR, 0);
    cudaStreamWaitEvent(0, evAux, 0);
    k_conv<1><<<gNW, T>>>(p_xwh, nullptr, p_cvh, gn1w, gn1b, n);

    k_gemm_tc<COUT, 0, 1, 0, 0, 1><<<GG, 256, SM128>>>(nullptr, p_cvh, W2, nullptr, nullptr, p_xwh,
                                                       nullptr, nullptr, nullptr, nullptr, n);
    k_conv<0><<<gNW, T>>>(p_xwh, p_res, p_cvh, gn2w, gn2b, n);

    k_gemm_tc<COUT, 0, 1, 0, 1, 1><<<GG, 256, SM128>>>(nullptr, p_cvh, Wa, nullptr, nullptr, p_hah,
                                                       nullptr, nullptr, asrc, adst, n);
    k_attn<<<gNW, T>>>(aedg, ba, out, n);
}